// round 6
// baseline (speedup 1.0000x reference)
#include <cuda_runtime.h>

// Problem constants
#define NB    256      // batch
#define NH    3        // heads
#define CC    64       // channels (c == o)
#define NN    23       // nodes
#define LL    35       // seq len
#define FEAT  529      // 23*23
#define LC    5        // l-chunk size
#define NCHUNK 7       // 35 / 5
#define KINV  (1.0f/2240.0f)   // 1/(o*l)

// ---------------- device scratch (no allocations allowed) ----------------
__device__ float g_G[NH*64*65];        // G[h][c2][c1], rows padded to 65
__device__ float g_v1[NH*CC];          // v1[h][c] = sum_o cb2[h,o]*cw1[h,o,c]
__device__ float g_v2[NH*CC];          // v2[h][c] = sum_o cb1[h,o]*cw2[h,o,c]
__device__ float g_sc[NH];             // sum_o cb1*cb2
__device__ float g_attm[NB*NH*FEAT];   // pre-BN attention
__device__ float g_scale[NH*FEAT];     // gamma/sqrt(var+eps)
__device__ float g_shift[NH*FEAT];     // beta - mean*scale
__device__ float g_A[NB*NH*FEAT];      // final adjacency
__device__ float g_gcn[NB*CC*NN*LL];   // gcn output before seq matmul

// ---------------- k0: precompute G, v1, v2, s ----------------
__global__ void k0_pre(const float* __restrict__ cw1, const float* __restrict__ cb1,
                       const float* __restrict__ cw2, const float* __restrict__ cb2) {
    __shared__ float s1[64*64];
    __shared__ float s2[64*64];
    int h = blockIdx.x, t = threadIdx.x;
    for (int i = t; i < 4096; i += 256) { s1[i] = cw1[h*4096+i]; s2[i] = cw2[h*4096+i]; }
    __syncthreads();
    for (int e = t; e < 4096; e += 256) {
        int c2 = e >> 6, c1 = e & 63;
        float acc = 0.f;
        #pragma unroll 8
        for (int o = 0; o < 64; o++) acc += s2[o*64+c2] * s1[o*64+c1];
        g_G[h*64*65 + c2*65 + c1] = acc;
    }
    if (t < 64) {
        float a1 = 0.f, a2 = 0.f;
        for (int o = 0; o < 64; o++) {
            a1 += cb2[h*64+o] * s1[o*64+t];
            a2 += cb1[h*64+o] * s2[o*64+t];
        }
        g_v1[h*64+t] = a1;
        g_v2[h*64+t] = a2;
    }
    if (t == 64) {
        float a = 0.f;
        for (int o = 0; o < 64; o++) a += cb1[h*64+o]*cb2[h*64+o];
        g_sc[h] = a;
    }
}

// ---------------- k1: attention matrices (pre-BN) ----------------
// per-block (one batch b): Q[h,m,n] = sum_l X_l^T G_h X_l, plus bias terms.
// smem: sG[3*64*65] | sxt[64*115] | sW[192*23] | sXs[64*23] | st1[69] | st2[69]
#define SM1_FLOATS (NH*64*65 + 64*115 + 192*23 + 64*23 + 69 + 69)

__global__ __launch_bounds__(256, 2) void k1_attm(const float* __restrict__ x) {
    extern __shared__ float sm[];
    float* sG  = sm;                    // 12480
    float* sxt = sG  + NH*64*65;        // 7360  : [c][n*5+li]
    float* sW  = sxt + 64*115;          // 4416  : [(h*64+c2)*23+n]
    float* sXs = sW  + 192*23;          // 1472  : [c*23+n]
    float* st1 = sXs + 64*23;           // 69
    float* st2 = st1 + 69;              // 69

    int b = blockIdx.x, t = threadIdx.x;

    for (int i = t; i < NH*64*65; i += 256) sG[i] = g_G[i];
    for (int i = t; i < 1472; i += 256) sXs[i] = 0.f;

    // W-phase mapping: 64 row-tiles (3 rows) x 4 col-tiles (6 cols)
    int rt = t & 63, ct = t >> 6;
    int r0 = rt * 3;
    int n0 = ct * 6;

    // Q-phase mapping: 192 active threads; tile 3m x 3n per head
    int qh = t / 64, qs = t % 64;
    int qmt = qs & 7, qnt = qs >> 3;
    bool qact = (t < 192);
    int m0 = qmt * 3, nq0 = qnt * 3;

    float q[3][3];
    #pragma unroll
    for (int i = 0; i < 3; i++)
        #pragma unroll
        for (int j = 0; j < 3; j++) q[i][j] = 0.f;

    __syncthreads();

    for (int ch = 0; ch < NCHUNK; ch++) {
        int l0 = ch * LC;
        for (int idx = t; idx < 7360; idx += 256) {
            int c = idx / 115, r = idx % 115;
            int n = r / 5, li = r % 5;
            sxt[idx] = x[((b*64 + c)*23 + n)*35 + l0 + li];
        }
        __syncthreads();

        // Xs accumulation (each entry owned by one thread, read only at the end)
        for (int e = t; e < 1472; e += 256) {
            float a = sXs[e];
            #pragma unroll
            for (int li = 0; li < 5; li++) a += sxt[e*5 + li];
            sXs[e] = a;
        }

        for (int li = 0; li < LC; li++) {
            // ---- W phase: W[h,c2,n] = sum_c1 G[h,c2,c1] * x[c1,n,li]
            float wacc[3][6];
            #pragma unroll
            for (int i = 0; i < 3; i++)
                #pragma unroll
                for (int j = 0; j < 6; j++) wacc[i][j] = 0.f;
            #pragma unroll 4
            for (int c1 = 0; c1 < 64; c1++) {
                float xv[6];
                #pragma unroll
                for (int j = 0; j < 6; j++) {
                    int nj = n0 + j; if (nj > 22) nj = 22;
                    xv[j] = sxt[c1*115 + nj*5 + li];
                }
                float gv[3];
                #pragma unroll
                for (int i = 0; i < 3; i++) gv[i] = sG[(r0 + i)*65 + c1];
                #pragma unroll
                for (int i = 0; i < 3; i++)
                    #pragma unroll
                    for (int j = 0; j < 6; j++) wacc[i][j] += gv[i] * xv[j];
            }
            #pragma unroll
            for (int i = 0; i < 3; i++)
                #pragma unroll
                for (int j = 0; j < 6; j++)
                    if (n0 + j < 23) sW[(r0 + i)*23 + n0 + j] = wacc[i][j];
            __syncthreads();

            // ---- Q phase: Q[h,m,n] += sum_c2 x[c2,m,li] * W[h,c2,n]
            if (qact) {
                #pragma unroll 4
                for (int c2 = 0; c2 < 64; c2++) {
                    float xm[3], wn[3];
                    #pragma unroll
                    for (int i = 0; i < 3; i++) {
                        int mi = m0 + i; if (mi > 22) mi = 22;
                        xm[i] = sxt[c2*115 + mi*5 + li];
                    }
                    #pragma unroll
                    for (int j = 0; j < 3; j++) {
                        int nj = nq0 + j; if (nj > 22) nj = 22;
                        wn[j] = sW[(qh*64 + c2)*23 + nj];
                    }
                    #pragma unroll
                    for (int i = 0; i < 3; i++)
                        #pragma unroll
                        for (int j = 0; j < 3; j++) q[i][j] += xm[i] * wn[j];
                }
            }
            __syncthreads();
        }
    }

    // bias-correction vectors
    if (t < 69) {
        int h = t / 23, n = t % 23;
        float a = 0.f;
        #pragma unroll 8
        for (int c = 0; c < 64; c++) a += g_v1[h*64 + c] * sXs[c*23 + n];
        st1[t] = a;
    } else if (t < 138) {
        int tt = t - 69;
        int h = tt / 23, m = tt % 23;
        float a = 0.f;
        #pragma unroll 8
        for (int c = 0; c < 64; c++) a += g_v2[h*64 + c] * sXs[c*23 + m];
        st2[tt] = a;
    }
    __syncthreads();

    if (qact) {
        float base = 35.0f * g_sc[qh];
        #pragma unroll
        for (int i = 0; i < 3; i++) {
            int m = m0 + i; if (m >= 23) continue;
            #pragma unroll
            for (int j = 0; j < 3; j++) {
                int n = nq0 + j; if (n >= 23) continue;
                float val = (q[i][j] + st2[qh*23 + m] + st1[qh*23 + n] + base) * KINV;
                g_attm[(b*NH + qh)*FEAT + m*23 + n] = val;
            }
        }
    }
}

// ---------------- k2: BN batch stats -> fused scale/shift ----------------
__global__ void k2_bn(const float* __restrict__ gamma, const float* __restrict__ beta) {
    __shared__ float ss[256];
    __shared__ float sq[256];
    int f = blockIdx.x;          // 0 .. 1586 = h*529 + feat
    int t = threadIdx.x;
    float v = g_attm[t*(NH*FEAT) + f];
    ss[t] = v; sq[t] = v*v;
    __syncthreads();
    for (int s = 128; s > 0; s >>= 1) {
        if (t < s) { ss[t] += ss[t+s]; sq[t] += sq[t+s]; }
        __syncthreads();
    }
    if (t == 0) {
        float mean = ss[0] * (1.0f/256.0f);
        float var  = sq[0] * (1.0f/256.0f) - mean*mean;
        float sc = gamma[f] * rsqrtf(var + 1e-5f);
        g_scale[f] = sc;
        g_shift[f] = beta[f] - mean * sc;
    }
}

// ---------------- k3: BN apply + softmax(axis=-2) + A assembly ----------------
__global__ void k3_soft(const float* __restrict__ att, const float* __restrict__ A_ske) {
    __shared__ float sy[FEAT];
    int bh = blockIdx.x;         // b*3 + h
    int h = bh % 3;
    int t = threadIdx.x;
    for (int e = t; e < FEAT; e += 256)
        sy[e] = g_attm[bh*FEAT + e] * g_scale[h*FEAT + e] + g_shift[h*FEAT + e];
    __syncthreads();
    if (t < 23) {   // softmax over rows m, column t
        float mx = -1e30f;
        for (int m = 0; m < 23; m++) mx = fmaxf(mx, sy[m*23 + t]);
        float s = 0.f;
        for (int m = 0; m < 23; m++) {
            float e = expf(sy[m*23 + t] - mx);
            sy[m*23 + t] = e; s += e;
        }
        float inv = 1.0f / s;
        for (int m = 0; m < 23; m++) sy[m*23 + t] *= inv;
    }
    __syncthreads();
    for (int e = t; e < FEAT; e += 256)
        g_A[bh*FEAT + e] = A_ske[h*FEAT + e] + att[h*FEAT + e] + sy[e];
}

// ---------------- k4: graph convolution -> g_gcn ----------------
// block = (b, l-chunk). MX[h] = mw[h] @ X_chunk, gcn += A[h]^T-contract(MX)
// smem: sA[3*529] | sxt[64*115] | sMX[64*115] | smw[64*65]
#define SM4_FLOATS (NH*FEAT + 64*115 + 64*115 + 64*65)

__global__ __launch_bounds__(256, 2) void k4_gcn(const float* __restrict__ x,
                                                 const float* __restrict__ mw,
                                                 const float* __restrict__ mb) {
    extern __shared__ float sm[];
    float* sA  = sm;                  // 1587
    float* sxt = sA  + NH*FEAT;       // 7360 : [c][n*5+li]
    float* sMX = sxt + 64*115;        // 7360 : [o][n*5+li]
    float* smw = sMX + 64*115;        // 4160 : [o*65+c]

    int blk = blockIdx.x;
    int b = blk / NCHUNK, ch = blk % NCHUNK;
    int l0 = ch * LC;
    int t = threadIdx.x;

    for (int i = t; i < NH*FEAT; i += 256) sA[i] = g_A[b*NH*FEAT + i];
    for (int idx = t; idx < 7360; idx += 256) {
        int c = idx / 115, r = idx % 115;
        int n = r / 5, li = r % 5;
        sxt[idx] = x[((b*64 + c)*23 + n)*35 + l0 + li];
    }

    // MX mapping: 16 o-tiles (stride-16 interleave, 4 rows) x 15 col-tiles (8 cols)
    int ot = t & 15, qt = t >> 4;
    bool mact = (qt < 15);
    int col0 = qt * 8;

    // gcn accumulator mapping: o = t%64, m-tile = t/64 (6 m) x 5 li
    int go = t & 63, gmt = t >> 6;
    int gm0 = gmt * 6;
    float gacc[6][5];
    #pragma unroll
    for (int j = 0; j < 6; j++)
        #pragma unroll
        for (int li = 0; li < 5; li++) gacc[j][li] = 0.f;

    __syncthreads();

    for (int h = 0; h < NH; h++) {
        for (int i = t; i < 4096; i += 256) {
            int o = i >> 6, c = i & 63;
            smw[o*65 + c] = mw[(h*64 + o)*64 + c];
        }
        __syncthreads();

        // MX = mw[h] @ X  (outputs 64 x 115)
        if (mact) {
            float acc[4][8];
            #pragma unroll
            for (int i = 0; i < 4; i++)
                #pragma unroll
                for (int j = 0; j < 8; j++) acc[i][j] = 0.f;
            #pragma unroll 4
            for (int c = 0; c < 64; c++) {
                float wv[4], xv[8];
                #pragma unroll
                for (int i = 0; i < 4; i++) wv[i] = smw[(ot + i*16)*65 + c];
                #pragma unroll
                for (int j = 0; j < 8; j++) {
                    int col = col0 + j;
                    xv[j] = (col < 115) ? sxt[c*115 + col] : 0.f;
                }
                #pragma unroll
                for (int i = 0; i < 4; i++)
                    #pragma unroll
                    for (int j = 0; j < 8; j++) acc[i][j] += wv[i] * xv[j];
            }
            #pragma unroll
            for (int i = 0; i < 4; i++)
                #pragma unroll
                for (int j = 0; j < 8; j++) {
                    int col = col0 + j;
                    if (col < 115) sMX[(ot + i*16)*115 + col] = acc[i][j];
                }
        }
        __syncthreads();

        // gcn[o,m,li] += sum_n MX[o,n,li] * A[h,n,m]
        #pragma unroll 1
        for (int n = 0; n < 23; n++) {
            float mx[5], av[6];
            #pragma unroll
            for (int li = 0; li < 5; li++) mx[li] = sMX[go*115 + n*5 + li];
            #pragma unroll
            for (int j = 0; j < 6; j++) {
                int m = gm0 + j; if (m > 22) m = 22;
                av[j] = sA[h*FEAT + n*23 + m];
            }
            #pragma unroll
            for (int j = 0; j < 6; j++)
                #pragma unroll
                for (int li = 0; li < 5; li++) gacc[j][li] += av[j] * mx[li];
        }
        __syncthreads();
    }

    float mbs = mb[go] + mb[64 + go] + mb[128 + go];
    #pragma unroll
    for (int j = 0; j < 6; j++) {
        int m = gm0 + j; if (m >= 23) continue;
        #pragma unroll
        for (int li = 0; li < 5; li++)
            g_gcn[((b*64 + go)*23 + m)*35 + l0 + li] = gacc[j][li] + mbs;
    }
}

// ---------------- k5: out = gcn @ weight_seq + bias ----------------
__global__ void k5_out(const float* __restrict__ ws, const float* __restrict__ bias,
                       float* __restrict__ out) {
    __shared__ float sws[LL*LL];
    __shared__ float sb[LL];
    __shared__ float srow[280];
    int t = threadIdx.x;
    for (int i = t; i < LL*LL; i += 280) sws[i] = ws[i];
    if (t < LL) sb[t] = bias[t];
    int base = blockIdx.x * 280;
    srow[t] = g_gcn[base + t];
    __syncthreads();
    int r = t / 35, j = t % 35;
    float acc = sb[j];
    #pragma unroll
    for (int l = 0; l < 35; l++) acc += srow[r*35 + l] * sws[l*35 + j];
    out[base + t] = acc;
}

// ---------------- host launch ----------------
extern "C" void kernel_launch(void* const* d_in, const int* in_sizes, int n_in,
                              void* d_out, int out_size) {
    const float* x      = (const float*)d_in[0];
    const float* cw1    = (const float*)d_in[1];
    const float* cb1    = (const float*)d_in[2];
    const float* cw2    = (const float*)d_in[3];
    const float* cb2    = (const float*)d_in[4];
    const float* gamma  = (const float*)d_in[5];
    const float* beta   = (const float*)d_in[6];
    const float* mw     = (const float*)d_in[7];
    const float* mb     = (const float*)d_in[8];
    const float* att    = (const float*)d_in[9];
    const float* A_ske  = (const float*)d_in[10];
    const float* ws     = (const float*)d_in[11];
    const float* bias   = (const float*)d_in[12];
    float* out = (float*)d_out;

    cudaFuncSetAttribute(k1_attm, cudaFuncAttributeMaxDynamicSharedMemorySize,
                         SM1_FLOATS * (int)sizeof(float));
    cudaFuncSetAttribute(k4_gcn, cudaFuncAttributeMaxDynamicSharedMemorySize,
                         SM4_FLOATS * (int)sizeof(float));

    k0_pre<<<NH, 256>>>(cw1, cb1, cw2, cb2);
    k1_attm<<<NB, 256, SM1_FLOATS * sizeof(float)>>>(x);
    k2_bn<<<NH*FEAT, 256>>>(gamma, beta);
    k3_soft<<<NB*NH, 256>>>(att, A_ske);
    k4_gcn<<<NB*NCHUNK, 256, SM4_FLOATS * sizeof(float)>>>(x, mw, mb);
    k5_out<<<(NB*CC*NN*LL)/280, 280>>>(ws, bias, out);
}

// round 9
// speedup vs baseline: 1.3602x; 1.3602x over previous
#include <cuda_runtime.h>

#define NB 256
#define NH 3
#define CC 64
#define NN 23
#define LL 35
#define FEAT 529
#define KINV (1.0f/2240.0f)

typedef unsigned long long ull;

__device__ __forceinline__ void fma2(ull& d, ull a, ull b) {
    asm("fma.rn.f32x2 %0, %1, %2, %0;" : "+l"(d) : "l"(a), "l"(b));
}
__device__ __forceinline__ ull dup2(float v) {
    ull r; unsigned u = __float_as_uint(v);
    asm("mov.b64 %0, {%1, %1};" : "=l"(r) : "r"(u));
    return r;
}
__device__ __forceinline__ void unpk(ull v, float& lo, float& hi) {
    unsigned a, b;
    asm("mov.b64 {%0, %1}, %2;" : "=r"(a), "=r"(b) : "l"(v));
    lo = __uint_as_float(a); hi = __uint_as_float(b);
}

// ---------------- device scratch ----------------
__device__ float g_GT[64*192];       // [c1*192 + h*64+c2]
__device__ float g_mwT[64*192];      // [c*192 + h*64+o]
__device__ float g_v1[NH*CC];
__device__ float g_v2[NH*CC];
__device__ float g_sc[NH];
__device__ float g_attm[NB*NH*FEAT];
__device__ float g_scale[NH*FEAT];
__device__ float g_shift[NH*FEAT];
__device__ float g_A[NB*NH*FEAT];
__device__ float g_gcn[NB*CC*NN*LL];

// ---------------- k0: G^T, v1, v2, s ----------------
__global__ void k0_pre(const float* __restrict__ cw1, const float* __restrict__ cb1,
                       const float* __restrict__ cw2, const float* __restrict__ cb2) {
    __shared__ float s1[4096];
    __shared__ float s2[4096];
    int h = blockIdx.x, t = threadIdx.x;
    for (int i = t; i < 4096; i += 256) { s1[i] = cw1[h*4096+i]; s2[i] = cw2[h*4096+i]; }
    __syncthreads();
    for (int e = t; e < 4096; e += 256) {
        int c2 = e >> 6, c1 = e & 63;
        float acc = 0.f;
        #pragma unroll 8
        for (int o = 0; o < 64; o++) acc += s2[o*64+c2] * s1[o*64+c1];
        g_GT[c1*192 + h*64 + c2] = acc;
    }
    if (t < 64) {
        float a1 = 0.f, a2 = 0.f;
        for (int o = 0; o < 64; o++) {
            a1 += cb2[h*64+o] * s1[o*64+t];
            a2 += cb1[h*64+o] * s2[o*64+t];
        }
        g_v1[h*64+t] = a1;
        g_v2[h*64+t] = a2;
    }
    if (t == 64) {
        float a = 0.f;
        for (int o = 0; o < 64; o++) a += cb1[h*64+o]*cb2[h*64+o];
        g_sc[h] = a;
    }
}

// ---------------- k0b: mw^T ----------------
__global__ void k0b_mwt(const float* __restrict__ mw) {
    int i = blockIdx.x * 256 + threadIdx.x;
    if (i < 12288) {
        int c = i / 192, row = i % 192;
        g_mwT[i] = mw[row*64 + c];
    }
}

// ---------------- k1: attention matrices, f32x2 over l-pairs ----------------
// smem floats: sGT 12288 | sxt 64*48 | sW2 192*50 | sXs 1472 | st1 72 | st2 72
#define SM1_FLOATS (12288 + 3072 + 9600 + 1472 + 72 + 72)

__global__ __launch_bounds__(256, 2) void k1_attm(const float* __restrict__ x) {
    extern __shared__ float sm[];
    float* sGT = sm;            // [c1*192 + row]
    float* sxt = sGT + 12288;   // [c*48 + n*2 + li], n padded to 24, zeros
    float* sW2 = sxt + 3072;    // [(row*25 + n)*2 + li], 25-pair row stride
    float* sXs = sW2 + 9600;    // [c*23 + n]
    float* st1 = sXs + 1472;
    float* st2 = st1 + 72;

    int b = blockIdx.x, t = threadIdx.x;

    for (int i = t; i < 12288; i += 256) sGT[i] = g_GT[i];
    for (int i = t; i < 1472; i += 256) sXs[i] = 0.f;

    // W-phase: rows r0..r0+2 of (h*64+c2) in 0..191; n-tile of 6
    int rt = t & 63, ct = t >> 6;
    int r0 = rt * 3, n0 = ct * 6;

    // Q-phase: t<192, qh = t>>6; 8x8 tiles of 3m x 3n
    int qh = t >> 6, s = t & 63;
    int m0 = (s & 7) * 3, nq0 = (s >> 3) * 3;
    bool qact = (t < 192);

    ull qp[3][3];
    #pragma unroll
    for (int i = 0; i < 3; i++)
        #pragma unroll
        for (int j = 0; j < 3; j++) qp[i][j] = 0ULL;

    const float* xb = x + b * (64*23*35);

    for (int p = 0; p < 18; p++) {
        int l0 = p * 2;
        __syncthreads();   // prev Q-phase reads done (and init on p=0)

        for (int idx = t; idx < 3072; idx += 256) {
            int c = idx / 48, r = idx - c*48;
            int n = r >> 1, li = r & 1;
            int l = l0 + li;
            sxt[idx] = (n < 23 && l < 35) ? xb[(c*23 + n)*35 + l] : 0.f;
        }
        __syncthreads();

        // Xs accumulation (owner-computes)
        for (int e = t; e < 1472; e += 256) {
            int c = e / 23, n = e - c*23;
            sXs[e] += sxt[c*48 + n*2] + sxt[c*48 + n*2 + 1];
        }

        // ---- W phase: W2[row][n] = sum_c1 G[row,c1] * x2[c1,n]
        {
            ull w2[3][6];
            #pragma unroll
            for (int i = 0; i < 3; i++)
                #pragma unroll
                for (int j = 0; j < 6; j++) w2[i][j] = 0ULL;
            #pragma unroll 4
            for (int c1 = 0; c1 < 64; c1++) {
                ull d0 = dup2(sGT[c1*192 + r0]);
                ull d1 = dup2(sGT[c1*192 + r0 + 1]);
                ull d2 = dup2(sGT[c1*192 + r0 + 2]);
                #pragma unroll
                for (int j = 0; j < 6; j++) {
                    ull xv = *reinterpret_cast<const ull*>(&sxt[c1*48 + (n0+j)*2]);
                    fma2(w2[0][j], d0, xv);
                    fma2(w2[1][j], d1, xv);
                    fma2(w2[2][j], d2, xv);
                }
            }
            #pragma unroll
            for (int i = 0; i < 3; i++)
                #pragma unroll
                for (int j = 0; j < 6; j++)
                    *reinterpret_cast<ull*>(&sW2[((r0+i)*25 + n0+j)*2]) = w2[i][j];
        }
        __syncthreads();

        // ---- Q phase: qp[m,n] += sum_c2 x2[c2,m] . W2[qh*64+c2, n]
        if (qact) {
            int wb = qh * 64;
            #pragma unroll 2
            for (int c2 = 0; c2 < 64; c2++) {
                ull xm[3], wn[3];
                #pragma unroll
                for (int i = 0; i < 3; i++)
                    xm[i] = *reinterpret_cast<const ull*>(&sxt[c2*48 + (m0+i)*2]);
                #pragma unroll
                for (int j = 0; j < 3; j++)
                    wn[j] = *reinterpret_cast<const ull*>(&sW2[((wb+c2)*25 + nq0+j)*2]);
                #pragma unroll
                for (int i = 0; i < 3; i++)
                    #pragma unroll
                    for (int j = 0; j < 3; j++)
                        fma2(qp[i][j], xm[i], wn[j]);
            }
        }
    }
    __syncthreads();

    if (t < 69) {
        int h = t / 23, n = t % 23;
        float a = 0.f;
        #pragma unroll 8
        for (int c = 0; c < 64; c++) a += g_v1[h*64 + c] * sXs[c*23 + n];
        st1[t] = a;
    } else if (t < 138) {
        int tt = t - 69;
        int h = tt / 23, m = tt % 23;
        float a = 0.f;
        #pragma unroll 8
        for (int c = 0; c < 64; c++) a += g_v2[h*64 + c] * sXs[c*23 + m];
        st2[tt] = a;
    }
    __syncthreads();

    if (qact) {
        float base = 35.0f * g_sc[qh];
        #pragma unroll
        for (int i = 0; i < 3; i++) {
            int m = m0 + i; if (m >= 23) continue;
            #pragma unroll
            for (int j = 0; j < 3; j++) {
                int n = nq0 + j; if (n >= 23) continue;
                float lo, hi; unpk(qp[i][j], lo, hi);
                float val = (lo + hi + st2[qh*23 + m] + st1[qh*23 + n] + base) * KINV;
                g_attm[(b*NH + qh)*FEAT + m*23 + n] = val;
            }
        }
    }
}

// ---------------- k2: BN stats ----------------
__global__ void k2_bn(const float* __restrict__ gamma, const float* __restrict__ beta) {
    __shared__ float ss[256];
    __shared__ float sq[256];
    int f = blockIdx.x, t = threadIdx.x;
    float v = g_attm[t*(NH*FEAT) + f];
    ss[t] = v; sq[t] = v*v;
    __syncthreads();
    for (int s = 128; s > 0; s >>= 1) {
        if (t < s) { ss[t] += ss[t+s]; sq[t] += sq[t+s]; }
        __syncthreads();
    }
    if (t == 0) {
        float mean = ss[0] * (1.0f/256.0f);
        float var  = sq[0] * (1.0f/256.0f) - mean*mean;
        float sc = gamma[f] * rsqrtf(var + 1e-5f);
        g_scale[f] = sc;
        g_shift[f] = beta[f] - mean * sc;
    }
}

// ---------------- k3: BN apply + softmax(-2) + A ----------------
__global__ void k3_soft(const float* __restrict__ att, const float* __restrict__ A_ske) {
    __shared__ float sy[FEAT];
    int bh = blockIdx.x, h = bh % 3, t = threadIdx.x;
    for (int e = t; e < FEAT; e += 256)
        sy[e] = g_attm[bh*FEAT + e] * g_scale[h*FEAT + e] + g_shift[h*FEAT + e];
    __syncthreads();
    if (t < 23) {
        float mx = -1e30f;
        for (int m = 0; m < 23; m++) mx = fmaxf(mx, sy[m*23 + t]);
        float ssum = 0.f;
        for (int m = 0; m < 23; m++) {
            float e = expf(sy[m*23 + t] - mx);
            sy[m*23 + t] = e; ssum += e;
        }
        float inv = 1.0f / ssum;
        for (int m = 0; m < 23; m++) sy[m*23 + t] *= inv;
    }
    __syncthreads();
    for (int e = t; e < FEAT; e += 256)
        g_A[bh*FEAT + e] = A_ske[h*FEAT + e] + att[h*FEAT + e] + sy[e];
}

// ---------------- k4: graph convolution, f32x2, l-chunks of 6 ----------------
// smem floats: sA 1588 (padded even for 8B alignment of the buffers after it)
//              | sxt 64*144 | sMX 64*146 | smwT 4096
#define SM4_FLOATS (1588 + 9216 + 9344 + 4096)

__global__ __launch_bounds__(256, 2) void k4_gcn(const float* __restrict__ x,
                                                 const float* __restrict__ mb) {
    extern __shared__ float sm[];
    float* sA   = sm;             // [h*529 + n*23 + m], padded to 1588
    float* sxt  = sA + 1588;      // [c*144 + n*6 + li], zero-pad  (8B-aligned)
    float* sMX  = sxt + 9216;     // [o*146 + n*6 + li]            (8B-aligned)
    float* smwT = sMX + 9344;     // [c*64 + o]

    int blk = blockIdx.x;
    int b = blk / 6, ch = blk % 6;
    int l0 = ch * 6;
    int t = threadIdx.x;

    for (int i = t; i < 1587; i += 256) sA[i] = g_A[b*1587 + i];
    for (int idx = t; idx < 9216; idx += 256) {
        int c = idx / 144, r = idx - c*144;
        int n = r / 6, li = r - n*6;
        int l = l0 + li;
        sxt[idx] = (n < 23 && l < 35) ? x[((b*64 + c)*23 + n)*35 + l] : 0.f;
    }

    // MX phase mapping: rows {ro, ro+32}, 9 pairs starting at pg0
    int ro = t & 31, pg0 = (t >> 5) * 9;

    // gcn mapping: o = t&63, m-tile of 6 at m0; 3 li-pairs
    int go = t & 63, m0 = (t >> 6) * 6;
    ull gacc[6][3];
    #pragma unroll
    for (int j = 0; j < 6; j++)
        #pragma unroll
        for (int lp = 0; lp < 3; lp++) gacc[j][lp] = 0ULL;

    for (int h = 0; h < NH; h++) {
        for (int i = t; i < 4096; i += 256)
            smwT[i] = g_mwT[(i >> 6)*192 + h*64 + (i & 63)];
        __syncthreads();  // prev gcn done + smwT/sxt ready

        // MX[o][col] = sum_c mw[h,o,c] * X[c,col]
        {
            ull a0[9], a1[9];
            #pragma unroll
            for (int q = 0; q < 9; q++) { a0[q] = 0ULL; a1[q] = 0ULL; }
            #pragma unroll 4
            for (int c = 0; c < 64; c++) {
                ull w0 = dup2(smwT[c*64 + ro]);
                ull w1 = dup2(smwT[c*64 + ro + 32]);
                #pragma unroll
                for (int q = 0; q < 9; q++) {
                    ull xv = *reinterpret_cast<const ull*>(&sxt[c*144 + 2*(pg0+q)]);
                    fma2(a0[q], w0, xv);
                    fma2(a1[q], w1, xv);
                }
            }
            #pragma unroll
            for (int q = 0; q < 9; q++) {
                *reinterpret_cast<ull*>(&sMX[ro*146 + 2*(pg0+q)]) = a0[q];
                *reinterpret_cast<ull*>(&sMX[(ro+32)*146 + 2*(pg0+q)]) = a1[q];
            }
        }
        __syncthreads();

        // gcn[o,m,li] += sum_n MX[o,n,li] * A[h,n,m]
        #pragma unroll 1
        for (int n = 0; n < 23; n++) {
            ull mx2[3];
            #pragma unroll
            for (int lp = 0; lp < 3; lp++)
                mx2[lp] = *reinterpret_cast<const ull*>(&sMX[go*146 + n*6 + 2*lp]);
            #pragma unroll
            for (int j = 0; j < 6; j++) {
                int m = m0 + j; if (m > 22) m = 22;
                ull av = dup2(sA[h*FEAT + n*23 + m]);
                #pragma unroll
                for (int lp = 0; lp < 3; lp++)
                    fma2(gacc[j][lp], av, mx2[lp]);
            }
        }
        __syncthreads();
    }

    float mbs = mb[go] + mb[64 + go] + mb[128 + go];
    #pragma unroll
    for (int j = 0; j < 6; j++) {
        int m = m0 + j; if (m >= 23) continue;
        #pragma unroll
        for (int lp = 0; lp < 3; lp++) {
            float lo, hi; unpk(gacc[j][lp], lo, hi);
            int l = l0 + 2*lp;
            float* dst = &g_gcn[((b*64 + go)*23 + m)*35 + l];
            if (l < 35)     dst[0] = lo + mbs;
            if (l + 1 < 35) dst[1] = hi + mbs;
        }
    }
}

// ---------------- k5: out = gcn @ ws + bias, f32x2, 64 rows/block ----------------
__global__ __launch_bounds__(288) void k5_out(const float* __restrict__ ws,
                                              const float* __restrict__ bias,
                                              float* __restrict__ out) {
    __shared__ float sws2[35*36];   // [l*36 + j], col 35 zero (base 0, even)
    __shared__ float sb[36];
    __shared__ float srow[64*35];
    int t = threadIdx.x;
    for (int i = t; i < 35*36; i += 288) {
        int l = i / 36, j = i - l*36;
        sws2[i] = (j < 35) ? ws[l*35 + j] : 0.f;
    }
    if (t < 36) sb[t] = (t < 35) ? bias[t] : 0.f;
    long long base = (long long)blockIdx.x * 2240;
    for (int i = t; i < 2240; i += 288) srow[i] = g_gcn[base + i];
    __syncthreads();

    int rg = t / 9, jg = t - rg*9;     // rg 0..31, jg 0..8
    int r0 = rg*2;
    ull a00 = 0ULL, a01 = 0ULL, a10 = 0ULL, a11 = 0ULL;
    #pragma unroll 5
    for (int l = 0; l < 35; l++) {
        ull w0 = *reinterpret_cast<const ull*>(&sws2[l*36 + 4*jg]);
        ull w1 = *reinterpret_cast<const ull*>(&sws2[l*36 + 4*jg + 2]);
        ull s0 = dup2(srow[r0*35 + l]);
        ull s1 = dup2(srow[r0*35 + 35 + l]);
        fma2(a00, s0, w0); fma2(a01, s0, w1);
        fma2(a10, s1, w0); fma2(a11, s1, w1);
    }

    float v[2][4];
    unpk(a00, v[0][0], v[0][1]); unpk(a01, v[0][2], v[0][3]);
    unpk(a10, v[1][0], v[1][1]); unpk(a11, v[1][2], v[1][3]);
    #pragma unroll
    for (int rr = 0; rr < 2; rr++) {
        long long ob = base + (long long)(r0 + rr) * 35;
        #pragma unroll
        for (int q = 0; q < 4; q++) {
            int j = 4*jg + q;
            if (j < 35) out[ob + j] = v[rr][q] + sb[j];
        }
    }
}

// ---------------- host launch ----------------
extern "C" void kernel_launch(void* const* d_in, const int* in_sizes, int n_in,
                              void* d_out, int out_size) {
    const float* x      = (const float*)d_in[0];
    const float* cw1    = (const float*)d_in[1];
    const float* cb1    = (const float*)d_in[2];
    const float* cw2    = (const float*)d_in[3];
    const float* cb2    = (const float*)d_in[4];
    const float* gamma  = (const float*)d_in[5];
    const float* beta   = (const float*)d_in[6];
    const float* mw     = (const float*)d_in[7];
    const float* mb     = (const float*)d_in[8];
    const float* att    = (const float*)d_in[9];
    const float* A_ske  = (const float*)d_in[10];
    const float* ws     = (const float*)d_in[11];
    const float* bias   = (const float*)d_in[12];
    float* out = (float*)d_out;

    cudaFuncSetAttribute(k1_attm, cudaFuncAttributeMaxDynamicSharedMemorySize,
                         SM1_FLOATS * (int)sizeof(float));
    cudaFuncSetAttribute(k4_gcn, cudaFuncAttributeMaxDynamicSharedMemorySize,
                         SM4_FLOATS * (int)sizeof(float));

    k0_pre<<<NH, 256>>>(cw1, cb1, cw2, cb2);
    k0b_mwt<<<48, 256>>>(mw);
    k1_attm<<<NB, 256, SM1_FLOATS * sizeof(float)>>>(x);
    k2_bn<<<NH*FEAT, 256>>>(gamma, beta);
    k3_soft<<<NB*NH, 256>>>(att, A_ske);
    k4_gcn<<<NB*6, 256, SM4_FLOATS * sizeof(float)>>>(x, mb);
    k5_out<<<5888, 288>>>(ws, bias, out);   // NB*CC*NN*LL / 2240 = 5888 blocks, 64 rows each
}